// round 11
// baseline (speedup 1.0000x reference)
#include <cuda_runtime.h>
#include <cuda_fp16.h>
#include <math.h>

#define NN 50000
#define EE 800000
#define ET 850000      // EE + NN self loops
#define FIN 128
#define HC 256         // HEADS*HID
#define NG 500
#define SLOPE 0.2f
#define BNEPS 1e-5f

// ---------------- scratch (device globals; no runtime allocation) -------------
__device__ __align__(256) __half g_hh[(size_t)NN * HC];   // GEMM output (fp16)
__device__ __align__(256) __half g_yh[(size_t)NN * HC];   // layer output (fp16)
__device__ __align__(256) __half g_xh[(size_t)NN * FIN];  // x converted to fp16
__device__ __align__(256) __half g_wt1[HC * FIN];         // W1^T fp16 [n][k]
__device__ __align__(256) __half g_wt2[HC * HC];          // W2^T fp16 [n][k]
__device__ float4 g_as[NN];
__device__ float4 g_ad[NN];
__device__ int    g_srcsort[ET];
__device__ int    g_deg[NN];
__device__ int    g_rowptr[NN + 1];
__device__ int    g_cursor[NN];
__device__ __align__(256) float  g_pooled[NG * HC];
__device__ int    g_src[EE];
__device__ int    g_dst[EE];
__device__ int    g_batch[NN];
__device__ int    g_is64;
#define SCAN_B 256
#define NB ((NN + SCAN_B - 1) / SCAN_B)    // 196
__device__ int    g_bsum[NB];
__device__ int    g_boff[NB];

// ---------------- dtype detect ------------------------------------------------
__global__ void detect_kernel(const unsigned* __restrict__ eiw, int* __restrict__ is64) {
    __shared__ int s_any;
    if (threadIdx.x == 0) s_any = 0;
    __syncthreads();
    unsigned v = eiw[threadIdx.x * 2 + 1];
    if (v != 0u) atomicOr(&s_any, 1);
    __syncthreads();
    if (threadIdx.x == 0) *is64 = s_any ? 0 : 1;
}

// ------- preconvert: x->fp16, W1/W2 -> transposed fp16, deg=1 (self loop) -----
__global__ void preconv_kernel(const float* __restrict__ x,
                               const float* __restrict__ W1,
                               const float* __restrict__ W2,
                               __half* __restrict__ xh,
                               __half* __restrict__ wt1,
                               __half* __restrict__ wt2,
                               int* __restrict__ deg) {
    int i = blockIdx.x * blockDim.x + threadIdx.x;
    int i4 = i * 4;
    if (i4 < NN * FIN) {
        float4 v = *(const float4*)(x + i4);
        __half2* o = (__half2*)(xh + i4);
        o[0] = __floats2half2_rn(v.x, v.y);
        o[1] = __floats2half2_rn(v.z, v.w);
    }
    if (i < NN) deg[i] = 1;
    if (i < HC * HC) {
        int n = i >> 8, k = i & 255;
        wt2[n * HC + k] = __float2half_rn(W2[k * HC + n]);
    }
    if (i < HC * FIN) {
        int n = i / FIN, k = i % FIN;
        wt1[n * FIN + k] = __float2half_rn(W1[k * HC + n]);
    }
}

// ---------------- prep: index conversion + batch + degree count ----------------
__global__ void prep_kernel(const void* __restrict__ ei, const void* __restrict__ b,
                            const int* __restrict__ is64,
                            int* __restrict__ src, int* __restrict__ dst,
                            int* __restrict__ batch, int* __restrict__ deg) {
    int i = blockIdx.x * blockDim.x + threadIdx.x;
    int w = *is64;
    if (i < EE) {
        int s, d;
        if (w) {
            const long long* p = (const long long*)ei;
            s = (int)p[i];
            d = (int)p[EE + i];
        } else {
            const int* p = (const int*)ei;
            s = p[i];
            d = p[EE + i];
        }
        src[i] = s;
        dst[i] = d;
        atomicAdd(&deg[d], 1);
    }
    if (i < NN) {
        batch[i] = w ? (int)((const long long*)b)[i] : ((const int*)b)[i];
    }
}

// ---------------- hierarchical scan -------------------------------------------
__global__ void blocksum_kernel(const int* __restrict__ deg, int* __restrict__ bsum) {
    __shared__ int sd[SCAN_B];
    int tid = threadIdx.x;
    int i = blockIdx.x * SCAN_B + tid;
    sd[tid] = (i < NN) ? deg[i] : 0;
    __syncthreads();
    for (int off = SCAN_B / 2; off; off >>= 1) {
        if (tid < off) sd[tid] += sd[tid + off];
        __syncthreads();
    }
    if (tid == 0) bsum[blockIdx.x] = sd[0];
}

__global__ void scanb_kernel(const int* __restrict__ bsum, int* __restrict__ boff) {
    __shared__ int sd[256];
    int tid = threadIdx.x;
    int v = (tid < NB) ? bsum[tid] : 0;
    sd[tid] = v;
    __syncthreads();
    for (int off = 1; off < 256; off <<= 1) {
        int t = (tid >= off) ? sd[tid - off] : 0;
        __syncthreads();
        sd[tid] += t;
        __syncthreads();
    }
    if (tid < NB) boff[tid] = sd[tid] - v;
}

__global__ void scatter_kernel(const int* __restrict__ deg, const int* __restrict__ boff,
                               int* __restrict__ rowptr, int* __restrict__ cursor) {
    __shared__ int sd[SCAN_B];
    int tid = threadIdx.x;
    int i = blockIdx.x * SCAN_B + tid;
    int v = (i < NN) ? deg[i] : 0;
    sd[tid] = v;
    __syncthreads();
    for (int off = 1; off < SCAN_B; off <<= 1) {
        int t = (tid >= off) ? sd[tid - off] : 0;
        __syncthreads();
        sd[tid] += t;
        __syncthreads();
    }
    int base = boff[blockIdx.x];
    if (i < NN) {
        rowptr[i + 1] = base + sd[tid];
        cursor[i] = base + sd[tid] - v;
    }
    if (i == 0) rowptr[0] = 0;
}

__global__ void fill_kernel(const int* __restrict__ esrc, const int* __restrict__ edst,
                            int* __restrict__ cursor, int* __restrict__ srcsort) {
    int eid = blockIdx.x * blockDim.x + threadIdx.x;
    if (eid >= ET) return;
    int s, d;
    if (eid < EE) { s = esrc[eid]; d = edst[eid]; }
    else          { s = eid - EE; d = s; }
    int pos = atomicAdd(&cursor[d], 1);
    srcsort[pos] = s;
}

// ---------------- fp16 tensor-core GEMM: C = A[M,K] @ Bt[n][k]^T ---------------
#define BM 128
#define BN 128
#define HS 24          // smem row stride (halves)

__global__ __launch_bounds__(256) void hgemm_kernel(const __half* __restrict__ A,
                                                    const __half* __restrict__ Bt,
                                                    __half* __restrict__ C,
                                                    int M, int K) {
    __shared__ __half As[2][BM * HS];
    __shared__ __half Bs[2][BM * HS];

    int tid = threadIdx.x;
    int warp = tid >> 5, lane = tid & 31;
    int warpM = (warp & 3) * 32;
    int warpN = (warp >> 2) * 64;
    int rowBase = blockIdx.y * BM;
    int colBase = blockIdx.x * BN;

    int fr = tid >> 1;
    int fk = (tid & 1) * 8;
    int gr = rowBase + fr;
    const uint4 z4 = make_uint4(0u, 0u, 0u, 0u);

    uint4 av, bv;

    av = (gr < M) ? *(const uint4*)(A + (size_t)gr * K + fk) : z4;
    bv = *(const uint4*)(Bt + (size_t)(colBase + fr) * K + fk);
    *(uint4*)(&As[0][fr * HS + fk]) = av;
    *(uint4*)(&Bs[0][fr * HS + fk]) = bv;
    __syncthreads();

    float d[2][8][4];
#pragma unroll
    for (int i = 0; i < 2; i++)
#pragma unroll
        for (int j = 0; j < 8; j++)
#pragma unroll
            for (int q = 0; q < 4; q++) d[i][j][q] = 0.f;

    int T = K / 16;
    int lr = lane >> 2;
    int lc = lane & 3;

    for (int t = 0; t < T; t++) {
        int buf = t & 1;
        if (t + 1 < T) {
            int k0 = (t + 1) * 16;
            av = (gr < M) ? *(const uint4*)(A + (size_t)gr * K + k0 + fk) : z4;
            bv = *(const uint4*)(Bt + (size_t)(colBase + fr) * K + k0 + fk);
        }

        unsigned af[2][4], bf[8][2];
#pragma unroll
        for (int mt = 0; mt < 2; mt++) {
            int r = warpM + 16 * mt + lr;
            af[mt][0] = *(const unsigned*)(&As[buf][r * HS + 2 * lc]);
            af[mt][1] = *(const unsigned*)(&As[buf][(r + 8) * HS + 2 * lc]);
            af[mt][2] = *(const unsigned*)(&As[buf][r * HS + 2 * lc + 8]);
            af[mt][3] = *(const unsigned*)(&As[buf][(r + 8) * HS + 2 * lc + 8]);
        }
#pragma unroll
        for (int nt = 0; nt < 8; nt++) {
            int n = warpN + 8 * nt + lr;
            bf[nt][0] = *(const unsigned*)(&Bs[buf][n * HS + 2 * lc]);
            bf[nt][1] = *(const unsigned*)(&Bs[buf][n * HS + 2 * lc + 8]);
        }
#pragma unroll
        for (int mt = 0; mt < 2; mt++)
#pragma unroll
            for (int nt = 0; nt < 8; nt++) {
                asm volatile(
                    "mma.sync.aligned.m16n8k16.row.col.f32.f16.f16.f32 "
                    "{%0,%1,%2,%3}, {%4,%5,%6,%7}, {%8,%9}, {%0,%1,%2,%3};"
                    : "+f"(d[mt][nt][0]), "+f"(d[mt][nt][1]),
                      "+f"(d[mt][nt][2]), "+f"(d[mt][nt][3])
                    : "r"(af[mt][0]), "r"(af[mt][1]), "r"(af[mt][2]), "r"(af[mt][3]),
                      "r"(bf[nt][0]), "r"(bf[nt][1]));
            }

        if (t + 1 < T) {
            int nb = buf ^ 1;
            *(uint4*)(&As[nb][fr * HS + fk]) = av;
            *(uint4*)(&Bs[nb][fr * HS + fk]) = bv;
            __syncthreads();
        }
    }

#pragma unroll
    for (int mt = 0; mt < 2; mt++) {
        int r0 = rowBase + warpM + 16 * mt + lr;
        int r1 = r0 + 8;
#pragma unroll
        for (int nt = 0; nt < 8; nt++) {
            int c = colBase + warpN + 8 * nt + 2 * lc;
            if (r0 < M)
                *(__half2*)(C + (size_t)r0 * HC + c) = __floats2half2_rn(d[mt][nt][0], d[mt][nt][1]);
            if (r1 < M)
                *(__half2*)(C + (size_t)r1 * HC + c) = __floats2half2_rn(d[mt][nt][2], d[mt][nt][3]);
        }
    }
}

// ---------------- per-node attention logits (vectorized fp16 reads) ------------
__global__ void asad_kernel(const __half* __restrict__ hh,
                            const float* __restrict__ att_src,
                            const float* __restrict__ att_dst,
                            float4* __restrict__ as_out,
                            float4* __restrict__ ad_out) {
    int warp = (blockIdx.x * blockDim.x + threadIdx.x) >> 5;
    int lid = threadIdx.x & 31;
    if (warp >= NN) return;
    // lane owns 8 contiguous channels [8*lid, 8*lid+8) -> one head (lid>>3)
    uint4 hv = ((const uint4*)(hh + (size_t)warp * HC))[lid];
    float2 f0 = __half22float2(*(__half2*)&hv.x);
    float2 f1 = __half22float2(*(__half2*)&hv.y);
    float2 f2 = __half22float2(*(__half2*)&hv.z);
    float2 f3 = __half22float2(*(__half2*)&hv.w);
    int c0 = lid * 8;
    float4 s0 = *(const float4*)(att_src + c0);
    float4 s1 = *(const float4*)(att_src + c0 + 4);
    float4 d0 = *(const float4*)(att_dst + c0);
    float4 d1 = *(const float4*)(att_dst + c0 + 4);
    float ps = f0.x * s0.x + f0.y * s0.y + f1.x * s0.z + f1.y * s0.w
             + f2.x * s1.x + f2.y * s1.y + f3.x * s1.z + f3.y * s1.w;
    float pd = f0.x * d0.x + f0.y * d0.y + f1.x * d0.z + f1.y * d0.w
             + f2.x * d1.x + f2.y * d1.y + f3.x * d1.z + f3.y * d1.w;
    // reduce within each head group of 8 lanes
#pragma unroll
    for (int off = 4; off; off >>= 1) {
        ps += __shfl_xor_sync(0xFFFFFFFFu, ps, off);
        pd += __shfl_xor_sync(0xFFFFFFFFu, pd, off);
    }
    // lanes 0,8,16,24 hold head sums; gather to lane 0
    float v0 = __shfl_sync(0xFFFFFFFFu, ps, 0);
    float v1 = __shfl_sync(0xFFFFFFFFu, ps, 8);
    float v2 = __shfl_sync(0xFFFFFFFFu, ps, 16);
    float v3 = __shfl_sync(0xFFFFFFFFu, ps, 24);
    float w0 = __shfl_sync(0xFFFFFFFFu, pd, 0);
    float w1 = __shfl_sync(0xFFFFFFFFu, pd, 8);
    float w2 = __shfl_sync(0xFFFFFFFFu, pd, 16);
    float w3 = __shfl_sync(0xFFFFFFFFu, pd, 24);
    if (lid == 0) {
        as_out[warp] = make_float4(v0, v1, v2, v3);
        ad_out[warp] = make_float4(w0, w1, w2, w3);
    }
}

// ---------------- fused single-pass softmax-aggregation + bias + relu + BN -----
__device__ __forceinline__ float4 leaky4(float4 a, float4 b) {
    float4 e;
    float v;
    v = a.x + b.x; e.x = (v > 0.f) ? v : SLOPE * v;
    v = a.y + b.y; e.y = (v > 0.f) ? v : SLOPE * v;
    v = a.z + b.z; e.z = (v > 0.f) ? v : SLOPE * v;
    v = a.w + b.w; e.w = (v > 0.f) ? v : SLOPE * v;
    return e;
}

__global__ __launch_bounds__(128) void agg_kernel(const int* __restrict__ srcsort,
                                                  const __half* __restrict__ hh,
                                                  const float4* __restrict__ as_in,
                                                  const float4* __restrict__ ad_in,
                                                  const int* __restrict__ rowptr,
                                                  __half* __restrict__ yh,
                                                  const float* __restrict__ bias,
                                                  const float* __restrict__ gam,
                                                  const float* __restrict__ bet,
                                                  const float* __restrict__ rmean,
                                                  const float* __restrict__ rvar) {
    int warp = (blockIdx.x * blockDim.x + threadIdx.x) >> 5;
    int lid = threadIdx.x & 31;
    if (warp >= NN) return;
    int beg = rowptr[warp], end = rowptr[warp + 1];
    float4 ad4 = ad_in[warp];
    int hsel = lid >> 3;       // head owned by this lane (8 contiguous channels)

    float acc[8] = {0.f, 0.f, 0.f, 0.f, 0.f, 0.f, 0.f, 0.f};
    float sp[4] = {0.f, 0.f, 0.f, 0.f};

    for (int base = beg; base < end; base += 32) {
        int j = base + lid;
        bool valid = j < end;
        int src = valid ? srcsort[j] : 0;
        float4 e4 = leaky4(as_in[src], ad4);
        float4 al;
        al.x = valid ? __expf(e4.x) : 0.f;
        al.y = valid ? __expf(e4.y) : 0.f;
        al.z = valid ? __expf(e4.z) : 0.f;
        al.w = valid ? __expf(e4.w) : 0.f;
        sp[0] += al.x; sp[1] += al.y; sp[2] += al.z; sp[3] += al.w;

        int nn = min(32, end - base);
        for (int i = 0; i < nn; i++) {
            int sj   = __shfl_sync(0xFFFFFFFFu, src, i);
            float a0 = __shfl_sync(0xFFFFFFFFu, al.x, i);
            float a1 = __shfl_sync(0xFFFFFFFFu, al.y, i);
            float a2 = __shfl_sync(0xFFFFFFFFu, al.z, i);
            float a3 = __shfl_sync(0xFFFFFFFFu, al.w, i);
            float a = (hsel == 0) ? a0 : (hsel == 1) ? a1 : (hsel == 2) ? a2 : a3;
            uint4 hv = ((const uint4*)(hh + (size_t)sj * HC))[lid];   // 16B/lane
            float2 f0 = __half22float2(*(__half2*)&hv.x);
            float2 f1 = __half22float2(*(__half2*)&hv.y);
            float2 f2 = __half22float2(*(__half2*)&hv.z);
            float2 f3 = __half22float2(*(__half2*)&hv.w);
            acc[0] = fmaf(f0.x, a, acc[0]);  acc[1] = fmaf(f0.y, a, acc[1]);
            acc[2] = fmaf(f1.x, a, acc[2]);  acc[3] = fmaf(f1.y, a, acc[3]);
            acc[4] = fmaf(f2.x, a, acc[4]);  acc[5] = fmaf(f2.y, a, acc[5]);
            acc[6] = fmaf(f3.x, a, acc[6]);  acc[7] = fmaf(f3.y, a, acc[7]);
        }
    }

#pragma unroll
    for (int off = 16; off; off >>= 1) {
#pragma unroll
        for (int k = 0; k < 4; k++)
            sp[k] += __shfl_xor_sync(0xFFFFFFFFu, sp[k], off);
    }
    float inv = 1.f / ((hsel == 0) ? sp[0] : (hsel == 1) ? sp[1] : (hsel == 2) ? sp[2] : sp[3]);

    int c0 = lid * 8;
    float4 bi0 = *(const float4*)(bias + c0);
    float4 bi1 = *(const float4*)(bias + c0 + 4);
    float4 ga0 = *(const float4*)(gam + c0);
    float4 ga1 = *(const float4*)(gam + c0 + 4);
    float4 be0 = *(const float4*)(bet + c0);
    float4 be1 = *(const float4*)(bet + c0 + 4);
    float4 rm0 = *(const float4*)(rmean + c0);
    float4 rm1 = *(const float4*)(rmean + c0 + 4);
    float4 rv0 = *(const float4*)(rvar + c0);
    float4 rv1 = *(const float4*)(rvar + c0 + 4);

    float o[8];
    o[0] = (fmaxf(acc[0] * inv + bi0.x, 0.f) - rm0.x) * rsqrtf(rv0.x + BNEPS) * ga0.x + be0.x;
    o[1] = (fmaxf(acc[1] * inv + bi0.y, 0.f) - rm0.y) * rsqrtf(rv0.y + BNEPS) * ga0.y + be0.y;
    o[2] = (fmaxf(acc[2] * inv + bi0.z, 0.f) - rm0.z) * rsqrtf(rv0.z + BNEPS) * ga0.z + be0.z;
    o[3] = (fmaxf(acc[3] * inv + bi0.w, 0.f) - rm0.w) * rsqrtf(rv0.w + BNEPS) * ga0.w + be0.w;
    o[4] = (fmaxf(acc[4] * inv + bi1.x, 0.f) - rm1.x) * rsqrtf(rv1.x + BNEPS) * ga1.x + be1.x;
    o[5] = (fmaxf(acc[5] * inv + bi1.y, 0.f) - rm1.y) * rsqrtf(rv1.y + BNEPS) * ga1.y + be1.y;
    o[6] = (fmaxf(acc[6] * inv + bi1.z, 0.f) - rm1.z) * rsqrtf(rv1.z + BNEPS) * ga1.z + be1.z;
    o[7] = (fmaxf(acc[7] * inv + bi1.w, 0.f) - rm1.w) * rsqrtf(rv1.w + BNEPS) * ga1.w + be1.w;

    uint4 ov;
    *(__half2*)&ov.x = __floats2half2_rn(o[0], o[1]);
    *(__half2*)&ov.y = __floats2half2_rn(o[2], o[3]);
    *(__half2*)&ov.z = __floats2half2_rn(o[4], o[5]);
    *(__half2*)&ov.w = __floats2half2_rn(o[6], o[7]);
    ((uint4*)(yh + (size_t)warp * HC))[lid] = ov;
}

// ---------------- pooling (fp16 in, fp32 accumulate) ---------------------------
__device__ __forceinline__ int lowerb(const int* b, int n, int key) {
    int lo = 0, hi = n;
    while (lo < hi) {
        int mid = (lo + hi) >> 1;
        if (b[mid] < key) lo = mid + 1; else hi = mid;
    }
    return lo;
}

__global__ void pool_kernel(const int* __restrict__ batch,
                            const __half* __restrict__ yh,
                            float* __restrict__ pooled) {
    int g = blockIdx.x;
    int c = threadIdx.x;     // 128 threads, each owns half2 channel pair
    __shared__ int s_lo, s_hi;
    if (c == 0) {
        s_lo = lowerb(batch, NN, g);
        s_hi = lowerb(batch, NN, g + 1);
    }
    __syncthreads();
    float sx = 0.f, sy = 0.f;
    const __half2* base = (const __half2*)yh;
    for (int n = s_lo; n < s_hi; n++) {
        float2 v = __half22float2(base[(size_t)n * (HC / 2) + c]);
        sx += v.x;
        sy += v.y;
    }
    int cnt = s_hi - s_lo;
    float denom = (cnt > 0) ? (float)cnt : 1.f;
    *(float2*)(pooled + g * HC + 2 * c) = make_float2(sx / denom, sy / denom);
}

// ---------------- MLP head -----------------------------------------------------
__global__ void head_kernel(const float* __restrict__ pooled,
                            const float* __restrict__ lw1, const float* __restrict__ lb1,
                            const float* __restrict__ lw2, const float* __restrict__ lb2,
                            float* __restrict__ out) {
    int g = blockIdx.x;
    int j = threadIdx.x;
    __shared__ float sp[256];
    __shared__ float r0[128], r1[128];
    sp[j] = pooled[g * HC + j];
    sp[j + 128] = pooled[g * HC + 128 + j];
    __syncthreads();
    float z = lb1[j];
#pragma unroll 4
    for (int k = 0; k < 256; k++) z = fmaf(sp[k], lw1[k * 128 + j], z);
    z = fmaxf(z, 0.f);
    r0[j] = z * lw2[j * 2 + 0];
    r1[j] = z * lw2[j * 2 + 1];
    __syncthreads();
    for (int off = 64; off; off >>= 1) {
        if (j < off) { r0[j] += r0[j + off]; r1[j] += r1[j + off]; }
        __syncthreads();
    }
    if (j == 0) {
        out[g * 2 + 0] = r0[0] + lb2[0];
        out[g * 2 + 1] = r1[0] + lb2[1];
    }
}

// ---------------- launcher ------------------------------------------------------
extern "C" void kernel_launch(void* const* d_in, const int* in_sizes, int n_in,
                              void* d_out, int out_size) {
    const float* x        = (const float*)d_in[0];
    const void*  ei       = d_in[1];
    const void*  batchraw = d_in[2];
    const float* W1       = (const float*)d_in[3];
    const float* att_src1 = (const float*)d_in[4];
    const float* att_dst1 = (const float*)d_in[5];
    const float* b1       = (const float*)d_in[6];
    const float* g1       = (const float*)d_in[7];
    const float* be1      = (const float*)d_in[8];
    const float* rm1      = (const float*)d_in[9];
    const float* rv1      = (const float*)d_in[10];
    const float* W2       = (const float*)d_in[11];
    const float* att_src2 = (const float*)d_in[12];
    const float* att_dst2 = (const float*)d_in[13];
    const float* b2       = (const float*)d_in[14];
    const float* g2       = (const float*)d_in[15];
    const float* be2      = (const float*)d_in[16];
    const float* rm2      = (const float*)d_in[17];
    const float* rv2      = (const float*)d_in[18];
    const float* lw1      = (const float*)d_in[19];
    const float* lb1      = (const float*)d_in[20];
    const float* lw2      = (const float*)d_in[21];
    const float* lb2      = (const float*)d_in[22];

    __half* p_hh = nullptr; __half* p_yh = nullptr;
    __half* p_xh = nullptr; __half* p_wt1 = nullptr; __half* p_wt2 = nullptr;
    float4* p_as = nullptr; float4* p_ad = nullptr; int* p_deg = nullptr;
    int* p_rowptr = nullptr; int* p_cursor = nullptr; int* p_srcsort = nullptr;
    float* p_pooled = nullptr; int* p_src = nullptr; int* p_dst = nullptr;
    int* p_batch = nullptr; int* p_is64 = nullptr;
    int* p_bsum = nullptr; int* p_boff = nullptr;
    cudaGetSymbolAddress((void**)&p_hh, g_hh);
    cudaGetSymbolAddress((void**)&p_yh, g_yh);
    cudaGetSymbolAddress((void**)&p_xh, g_xh);
    cudaGetSymbolAddress((void**)&p_wt1, g_wt1);
    cudaGetSymbolAddress((void**)&p_wt2, g_wt2);
    cudaGetSymbolAddress((void**)&p_as, g_as);
    cudaGetSymbolAddress((void**)&p_ad, g_ad);
    cudaGetSymbolAddress((void**)&p_deg, g_deg);
    cudaGetSymbolAddress((void**)&p_rowptr, g_rowptr);
    cudaGetSymbolAddress((void**)&p_cursor, g_cursor);
    cudaGetSymbolAddress((void**)&p_srcsort, g_srcsort);
    cudaGetSymbolAddress((void**)&p_pooled, g_pooled);
    cudaGetSymbolAddress((void**)&p_src, g_src);
    cudaGetSymbolAddress((void**)&p_dst, g_dst);
    cudaGetSymbolAddress((void**)&p_batch, g_batch);
    cudaGetSymbolAddress((void**)&p_is64, g_is64);
    cudaGetSymbolAddress((void**)&p_bsum, g_bsum);
    cudaGetSymbolAddress((void**)&p_boff, g_boff);

    dim3 ggrid(HC / BN, (NN + BM - 1) / BM);
    int aggBlocks = (NN * 32 + 127) / 128;
    int warpBlocks = (NN * 32 + 255) / 256;
    int pcBlocks = (NN * FIN / 4 + 255) / 256;

    // (1) detect (2) preconv (3) prep(+count) (4) hgemm1 <- profiled sentinel
    detect_kernel<<<1, 1024>>>((const unsigned*)ei, p_is64);
    preconv_kernel<<<pcBlocks, 256>>>(x, W1, W2, p_xh, p_wt1, p_wt2, p_deg);
    prep_kernel<<<(EE + 255) / 256, 256>>>(ei, batchraw, p_is64, p_src, p_dst,
                                           p_batch, p_deg);
    hgemm_kernel<<<ggrid, 256>>>(p_xh, p_wt1, p_hh, NN, FIN);

    // hierarchical scan + fill
    blocksum_kernel<<<NB, SCAN_B>>>(p_deg, p_bsum);
    scanb_kernel<<<1, 256>>>(p_bsum, p_boff);
    scatter_kernel<<<NB, SCAN_B>>>(p_deg, p_boff, p_rowptr, p_cursor);
    fill_kernel<<<(ET + 255) / 256, 256>>>(p_src, p_dst, p_cursor, p_srcsort);

    // ---- layer 1 ----
    asad_kernel<<<warpBlocks, 256>>>(p_hh, att_src1, att_dst1, p_as, p_ad);
    agg_kernel<<<aggBlocks, 128>>>(p_srcsort, p_hh, p_as, p_ad, p_rowptr, p_yh,
                                   b1, g1, be1, rm1, rv1);

    // ---- layer 2 ----
    hgemm_kernel<<<ggrid, 256>>>(p_yh, p_wt2, p_hh, NN, HC);
    asad_kernel<<<warpBlocks, 256>>>(p_hh, att_src2, att_dst2, p_as, p_ad);
    agg_kernel<<<aggBlocks, 128>>>(p_srcsort, p_hh, p_as, p_ad, p_rowptr, p_yh,
                                   b2, g2, be2, rm2, rv2);

    // ---- pool + head ----
    pool_kernel<<<NG, 128>>>(p_batch, p_yh, p_pooled);
    head_kernel<<<NG, 128>>>(p_pooled, lw1, lb1, lw2, lb2, (float*)d_out);
}

// round 12
// speedup vs baseline: 1.1268x; 1.1268x over previous
#include <cuda_runtime.h>
#include <cuda_fp16.h>
#include <math.h>

#define NN 50000
#define EE 800000
#define ET 850000      // EE + NN self loops
#define FIN 128
#define HC 256         // HEADS*HID
#define NG 500
#define SLOPE 0.2f
#define BNEPS 1e-5f

// ---------------- scratch (device globals; no runtime allocation) -------------
__device__ __align__(256) __half g_hh[(size_t)NN * HC];   // GEMM output (fp16)
__device__ __align__(256) __half g_yh[(size_t)NN * HC];   // layer output (fp16)
__device__ __align__(256) float  g_y[(size_t)NN * HC];    // layer-2 output (fp32)
__device__ __align__(256) __half g_xh[(size_t)NN * FIN];  // x converted to fp16
__device__ __align__(256) __half g_wt1[HC * FIN];         // W1^T fp16 [n][k]
__device__ __align__(256) __half g_wt2[HC * HC];          // W2^T fp16 [n][k]
__device__ float4 g_as[NN];
__device__ float4 g_ad[NN];
__device__ int    g_srcsort[ET];
__device__ int    g_deg[NN];
__device__ int    g_rowptr[NN + 1];
__device__ int    g_cursor[NN];
__device__ __align__(256) float  g_pooled[NG * HC];
__device__ int    g_src[EE];
__device__ int    g_dst[EE];
__device__ int    g_batch[NN];
__device__ int    g_is64;
#define SCAN_B 256
#define NB ((NN + SCAN_B - 1) / SCAN_B)    // 196
__device__ int    g_bsum[NB];
__device__ int    g_boff[NB];

// ---------------- dtype detect ------------------------------------------------
__global__ void detect_kernel(const unsigned* __restrict__ eiw, int* __restrict__ is64) {
    __shared__ int s_any;
    if (threadIdx.x == 0) s_any = 0;
    __syncthreads();
    unsigned v = eiw[threadIdx.x * 2 + 1];
    if (v != 0u) atomicOr(&s_any, 1);
    __syncthreads();
    if (threadIdx.x == 0) *is64 = s_any ? 0 : 1;
}

// ------- preconvert: x->fp16, W^T fp16, deg=1, zero as/ad ----------------------
__global__ void preconv_kernel(const float* __restrict__ x,
                               const float* __restrict__ W1,
                               const float* __restrict__ W2,
                               __half* __restrict__ xh,
                               __half* __restrict__ wt1,
                               __half* __restrict__ wt2,
                               int* __restrict__ deg,
                               float* __restrict__ asf,
                               float* __restrict__ adf) {
    int i = blockIdx.x * blockDim.x + threadIdx.x;
    int i4 = i * 4;
    if (i4 < NN * FIN) {
        float4 v = *(const float4*)(x + i4);
        __half2* o = (__half2*)(xh + i4);
        o[0] = __floats2half2_rn(v.x, v.y);
        o[1] = __floats2half2_rn(v.z, v.w);
    }
    if (i < NN) deg[i] = 1;
    if (i < NN * 4) { asf[i] = 0.f; adf[i] = 0.f; }
    if (i < HC * HC) {
        int n = i >> 8, k = i & 255;
        wt2[n * HC + k] = __float2half_rn(W2[k * HC + n]);
    }
    if (i < HC * FIN) {
        int n = i / FIN, k = i % FIN;
        wt1[n * FIN + k] = __float2half_rn(W1[k * HC + n]);
    }
}

// ---------------- zero as/ad between layers ------------------------------------
__global__ void zeroasad_kernel(float* __restrict__ asf, float* __restrict__ adf) {
    int i = blockIdx.x * blockDim.x + threadIdx.x;
    if (i < NN * 4) { asf[i] = 0.f; adf[i] = 0.f; }
}

// ---------------- prep: index conversion + batch + degree count ----------------
__global__ void prep_kernel(const void* __restrict__ ei, const void* __restrict__ b,
                            const int* __restrict__ is64,
                            int* __restrict__ src, int* __restrict__ dst,
                            int* __restrict__ batch, int* __restrict__ deg) {
    int i = blockIdx.x * blockDim.x + threadIdx.x;
    int w = *is64;
    if (i < EE) {
        int s, d;
        if (w) {
            const long long* p = (const long long*)ei;
            s = (int)p[i];
            d = (int)p[EE + i];
        } else {
            const int* p = (const int*)ei;
            s = p[i];
            d = p[EE + i];
        }
        src[i] = s;
        dst[i] = d;
        atomicAdd(&deg[d], 1);
    }
    if (i < NN) {
        batch[i] = w ? (int)((const long long*)b)[i] : ((const int*)b)[i];
    }
}

// ---------------- hierarchical scan -------------------------------------------
__global__ void blocksum_kernel(const int* __restrict__ deg, int* __restrict__ bsum) {
    __shared__ int sd[SCAN_B];
    int tid = threadIdx.x;
    int i = blockIdx.x * SCAN_B + tid;
    sd[tid] = (i < NN) ? deg[i] : 0;
    __syncthreads();
    for (int off = SCAN_B / 2; off; off >>= 1) {
        if (tid < off) sd[tid] += sd[tid + off];
        __syncthreads();
    }
    if (tid == 0) bsum[blockIdx.x] = sd[0];
}

__global__ void scanb_kernel(const int* __restrict__ bsum, int* __restrict__ boff) {
    __shared__ int sd[256];
    int tid = threadIdx.x;
    int v = (tid < NB) ? bsum[tid] : 0;
    sd[tid] = v;
    __syncthreads();
    for (int off = 1; off < 256; off <<= 1) {
        int t = (tid >= off) ? sd[tid - off] : 0;
        __syncthreads();
        sd[tid] += t;
        __syncthreads();
    }
    if (tid < NB) boff[tid] = sd[tid] - v;
}

__global__ void scatter_kernel(const int* __restrict__ deg, const int* __restrict__ boff,
                               int* __restrict__ rowptr, int* __restrict__ cursor) {
    __shared__ int sd[SCAN_B];
    int tid = threadIdx.x;
    int i = blockIdx.x * SCAN_B + tid;
    int v = (i < NN) ? deg[i] : 0;
    sd[tid] = v;
    __syncthreads();
    for (int off = 1; off < SCAN_B; off <<= 1) {
        int t = (tid >= off) ? sd[tid - off] : 0;
        __syncthreads();
        sd[tid] += t;
        __syncthreads();
    }
    int base = boff[blockIdx.x];
    if (i < NN) {
        rowptr[i + 1] = base + sd[tid];
        cursor[i] = base + sd[tid] - v;
    }
    if (i == 0) rowptr[0] = 0;
}

__global__ void fill_kernel(const int* __restrict__ esrc, const int* __restrict__ edst,
                            int* __restrict__ cursor, int* __restrict__ srcsort) {
    int eid = blockIdx.x * blockDim.x + threadIdx.x;
    if (eid >= ET) return;
    int s, d;
    if (eid < EE) { s = esrc[eid]; d = edst[eid]; }
    else          { s = eid - EE; d = s; }
    int pos = atomicAdd(&cursor[d], 1);
    srcsort[pos] = s;
}

// ------ fp16 tensor-core GEMM + fused attention-logit epilogue -----------------
// C = A[M,K] @ Bt[n][k]^T ; also atomically accumulates as/ad dot products.
#define BM 128
#define BN 128
#define HS 24          // smem row stride (halves)

__global__ __launch_bounds__(256) void hgemm_kernel(const __half* __restrict__ A,
                                                    const __half* __restrict__ Bt,
                                                    __half* __restrict__ C,
                                                    const float* __restrict__ att_src,
                                                    const float* __restrict__ att_dst,
                                                    float* __restrict__ asf,
                                                    float* __restrict__ adf,
                                                    int M, int K) {
    __shared__ __half As[2][BM * HS];
    __shared__ __half Bs[2][BM * HS];

    int tid = threadIdx.x;
    int warp = tid >> 5, lane = tid & 31;
    int warpM = (warp & 3) * 32;
    int warpN = (warp >> 2) * 64;
    int rowBase = blockIdx.y * BM;
    int colBase = blockIdx.x * BN;

    int fr = tid >> 1;
    int fk = (tid & 1) * 8;
    int gr = rowBase + fr;
    const uint4 z4 = make_uint4(0u, 0u, 0u, 0u);

    uint4 av, bv;

    av = (gr < M) ? *(const uint4*)(A + (size_t)gr * K + fk) : z4;
    bv = *(const uint4*)(Bt + (size_t)(colBase + fr) * K + fk);
    *(uint4*)(&As[0][fr * HS + fk]) = av;
    *(uint4*)(&Bs[0][fr * HS + fk]) = bv;
    __syncthreads();

    float d[2][8][4];
#pragma unroll
    for (int i = 0; i < 2; i++)
#pragma unroll
        for (int j = 0; j < 8; j++)
#pragma unroll
            for (int q = 0; q < 4; q++) d[i][j][q] = 0.f;

    int T = K / 16;
    int lr = lane >> 2;
    int lc = lane & 3;

    for (int t = 0; t < T; t++) {
        int buf = t & 1;
        if (t + 1 < T) {
            int k0 = (t + 1) * 16;
            av = (gr < M) ? *(const uint4*)(A + (size_t)gr * K + k0 + fk) : z4;
            bv = *(const uint4*)(Bt + (size_t)(colBase + fr) * K + k0 + fk);
        }

        unsigned af[2][4], bf[8][2];
#pragma unroll
        for (int mt = 0; mt < 2; mt++) {
            int r = warpM + 16 * mt + lr;
            af[mt][0] = *(const unsigned*)(&As[buf][r * HS + 2 * lc]);
            af[mt][1] = *(const unsigned*)(&As[buf][(r + 8) * HS + 2 * lc]);
            af[mt][2] = *(const unsigned*)(&As[buf][r * HS + 2 * lc + 8]);
            af[mt][3] = *(const unsigned*)(&As[buf][(r + 8) * HS + 2 * lc + 8]);
        }
#pragma unroll
        for (int nt = 0; nt < 8; nt++) {
            int n = warpN + 8 * nt + lr;
            bf[nt][0] = *(const unsigned*)(&Bs[buf][n * HS + 2 * lc]);
            bf[nt][1] = *(const unsigned*)(&Bs[buf][n * HS + 2 * lc + 8]);
        }
#pragma unroll
        for (int mt = 0; mt < 2; mt++)
#pragma unroll
            for (int nt = 0; nt < 8; nt++) {
                asm volatile(
                    "mma.sync.aligned.m16n8k16.row.col.f32.f16.f16.f32 "
                    "{%0,%1,%2,%3}, {%4,%5,%6,%7}, {%8,%9}, {%0,%1,%2,%3};"
                    : "+f"(d[mt][nt][0]), "+f"(d[mt][nt][1]),
                      "+f"(d[mt][nt][2]), "+f"(d[mt][nt][3])
                    : "r"(af[mt][0]), "r"(af[mt][1]), "r"(af[mt][2]), "r"(af[mt][3]),
                      "r"(bf[nt][0]), "r"(bf[nt][1]));
            }

        if (t + 1 < T) {
            int nb = buf ^ 1;
            *(uint4*)(&As[nb][fr * HS + fk]) = av;
            *(uint4*)(&Bs[nb][fr * HS + fk]) = bv;
            __syncthreads();
        }
    }

    // epilogue: store fp16 + fused attention-logit partial dots
    int hidx = (colBase + warpN) >> 6;   // this warp's 64 columns = one head
#pragma unroll
    for (int mt = 0; mt < 2; mt++) {
        int r0 = rowBase + warpM + 16 * mt + lr;
        int r1 = r0 + 8;
        float s0 = 0.f, s1 = 0.f, t0 = 0.f, t1 = 0.f;
#pragma unroll
        for (int nt = 0; nt < 8; nt++) {
            int c = colBase + warpN + 8 * nt + 2 * lc;
            float2 sv = *(const float2*)(att_src + c);
            float2 dv = *(const float2*)(att_dst + c);
            s0 = fmaf(d[mt][nt][0], sv.x, fmaf(d[mt][nt][1], sv.y, s0));
            s1 = fmaf(d[mt][nt][2], sv.x, fmaf(d[mt][nt][3], sv.y, s1));
            t0 = fmaf(d[mt][nt][0], dv.x, fmaf(d[mt][nt][1], dv.y, t0));
            t1 = fmaf(d[mt][nt][2], dv.x, fmaf(d[mt][nt][3], dv.y, t1));
            if (r0 < M)
                *(__half2*)(C + (size_t)r0 * HC + c) = __floats2half2_rn(d[mt][nt][0], d[mt][nt][1]);
            if (r1 < M)
                *(__half2*)(C + (size_t)r1 * HC + c) = __floats2half2_rn(d[mt][nt][2], d[mt][nt][3]);
        }
        // reduce across lc (lane = lr*4 + lc)
#pragma unroll
        for (int off = 1; off < 4; off <<= 1) {
            s0 += __shfl_xor_sync(0xFFFFFFFFu, s0, off);
            s1 += __shfl_xor_sync(0xFFFFFFFFu, s1, off);
            t0 += __shfl_xor_sync(0xFFFFFFFFu, t0, off);
            t1 += __shfl_xor_sync(0xFFFFFFFFu, t1, off);
        }
        if (lc == 0) {
            if (r0 < M) {
                atomicAdd(&asf[r0 * 4 + hidx], s0);
                atomicAdd(&adf[r0 * 4 + hidx], t0);
            }
            if (r1 < M) {
                atomicAdd(&asf[r1 * 4 + hidx], s1);
                atomicAdd(&adf[r1 * 4 + hidx], t1);
            }
        }
    }
}

// ---------------- fused single-pass softmax-aggregation + bias + relu + BN -----
__device__ __forceinline__ float4 leaky4(float4 a, float4 b) {
    float4 e;
    float v;
    v = a.x + b.x; e.x = (v > 0.f) ? v : SLOPE * v;
    v = a.y + b.y; e.y = (v > 0.f) ? v : SLOPE * v;
    v = a.z + b.z; e.z = (v > 0.f) ? v : SLOPE * v;
    v = a.w + b.w; e.w = (v > 0.f) ? v : SLOPE * v;
    return e;
}

__global__ __launch_bounds__(128) void agg_kernel(const int* __restrict__ srcsort,
                                                  const __half* __restrict__ hh,
                                                  const float4* __restrict__ as_in,
                                                  const float4* __restrict__ ad_in,
                                                  const int* __restrict__ rowptr,
                                                  __half* __restrict__ yh,
                                                  float* __restrict__ y32,
                                                  const float* __restrict__ bias,
                                                  const float* __restrict__ gam,
                                                  const float* __restrict__ bet,
                                                  const float* __restrict__ rmean,
                                                  const float* __restrict__ rvar) {
    int warp = (blockIdx.x * blockDim.x + threadIdx.x) >> 5;
    int lid = threadIdx.x & 31;
    if (warp >= NN) return;
    int beg = rowptr[warp], end = rowptr[warp + 1];
    float4 ad4 = ad_in[warp];

    float accx[4] = {0.f, 0.f, 0.f, 0.f};
    float accy[4] = {0.f, 0.f, 0.f, 0.f};
    float sp[4] = {0.f, 0.f, 0.f, 0.f};

    for (int base = beg; base < end; base += 32) {
        int j = base + lid;
        bool valid = j < end;
        int src = valid ? srcsort[j] : 0;
        float4 e4 = leaky4(as_in[src], ad4);
        float4 al;
        al.x = valid ? __expf(e4.x) : 0.f;
        al.y = valid ? __expf(e4.y) : 0.f;
        al.z = valid ? __expf(e4.z) : 0.f;
        al.w = valid ? __expf(e4.w) : 0.f;
        sp[0] += al.x; sp[1] += al.y; sp[2] += al.z; sp[3] += al.w;

        int nn = min(32, end - base);
        for (int i = 0; i < nn; i++) {
            int sj   = __shfl_sync(0xFFFFFFFFu, src, i);
            float a0 = __shfl_sync(0xFFFFFFFFu, al.x, i);
            float a1 = __shfl_sync(0xFFFFFFFFu, al.y, i);
            float a2 = __shfl_sync(0xFFFFFFFFu, al.z, i);
            float a3 = __shfl_sync(0xFFFFFFFFu, al.w, i);
            const __half2* hs = (const __half2*)(hh + (size_t)sj * HC);
            float2 v0 = __half22float2(hs[lid]);
            float2 v1 = __half22float2(hs[lid + 32]);
            float2 v2 = __half22float2(hs[lid + 64]);
            float2 v3 = __half22float2(hs[lid + 96]);
            accx[0] = fmaf(v0.x, a0, accx[0]);  accy[0] = fmaf(v0.y, a0, accy[0]);
            accx[1] = fmaf(v1.x, a1, accx[1]);  accy[1] = fmaf(v1.y, a1, accy[1]);
            accx[2] = fmaf(v2.x, a2, accx[2]);  accy[2] = fmaf(v2.y, a2, accy[2]);
            accx[3] = fmaf(v3.x, a3, accx[3]);  accy[3] = fmaf(v3.y, a3, accy[3]);
        }
    }

#pragma unroll
    for (int off = 16; off; off >>= 1) {
#pragma unroll
        for (int k = 0; k < 4; k++)
            sp[k] += __shfl_xor_sync(0xFFFFFFFFu, sp[k], off);
    }
    float inv[4];
#pragma unroll
    for (int k = 0; k < 4; k++) inv[k] = 1.f / sp[k];

    size_t ob = (size_t)warp * HC;
#pragma unroll
    for (int k = 0; k < 4; k++) {
        int c = 2 * lid + 64 * k;
        float2 bi = *(const float2*)(bias + c);
        float2 ga = *(const float2*)(gam + c);
        float2 be = *(const float2*)(bet + c);
        float2 rm = *(const float2*)(rmean + c);
        float2 rv = *(const float2*)(rvar + c);
        float vx = fmaxf(accx[k] * inv[k] + bi.x, 0.f);
        float vy = fmaxf(accy[k] * inv[k] + bi.y, 0.f);
        vx = (vx - rm.x) * rsqrtf(rv.x + BNEPS) * ga.x + be.x;
        vy = (vy - rm.y) * rsqrtf(rv.y + BNEPS) * ga.y + be.y;
        *(__half2*)(yh + ob + c) = __floats2half2_rn(vx, vy);
        if (y32) *(float2*)(y32 + ob + c) = make_float2(vx, vy);
    }
}

// ---------------- pooling ------------------------------------------------------
__device__ __forceinline__ int lowerb(const int* b, int n, int key) {
    int lo = 0, hi = n;
    while (lo < hi) {
        int mid = (lo + hi) >> 1;
        if (b[mid] < key) lo = mid + 1; else hi = mid;
    }
    return lo;
}

__global__ void pool_kernel(const int* __restrict__ batch,
                            const float* __restrict__ y,
                            float* __restrict__ pooled) {
    int g = blockIdx.x;
    int c = threadIdx.x;
    __shared__ int s_lo, s_hi;
    if (c == 0) {
        s_lo = lowerb(batch, NN, g);
        s_hi = lowerb(batch, NN, g + 1);
    }
    __syncthreads();
    float sum = 0.f;
    for (int n = s_lo; n < s_hi; n++) sum += y[(size_t)n * HC + c];
    int cnt = s_hi - s_lo;
    float denom = (cnt > 0) ? (float)cnt : 1.f;
    pooled[g * HC + c] = sum / denom;
}

// ---------------- MLP head -----------------------------------------------------
__global__ void head_kernel(const float* __restrict__ pooled,
                            const float* __restrict__ lw1, const float* __restrict__ lb1,
                            const float* __restrict__ lw2, const float* __restrict__ lb2,
                            float* __restrict__ out) {
    int g = blockIdx.x;
    int j = threadIdx.x;
    __shared__ float sp[256];
    __shared__ float r0[128], r1[128];
    sp[j] = pooled[g * HC + j];
    sp[j + 128] = pooled[g * HC + 128 + j];
    __syncthreads();
    float z = lb1[j];
#pragma unroll 4
    for (int k = 0; k < 256; k++) z = fmaf(sp[k], lw1[k * 128 + j], z);
    z = fmaxf(z, 0.f);
    r0[j] = z * lw2[j * 2 + 0];
    r1[j] = z * lw2[j * 2 + 1];
    __syncthreads();
    for (int off = 64; off; off >>= 1) {
        if (j < off) { r0[j] += r0[j + off]; r1[j] += r1[j + off]; }
        __syncthreads();
    }
    if (j == 0) {
        out[g * 2 + 0] = r0[0] + lb2[0];
        out[g * 2 + 1] = r1[0] + lb2[1];
    }
}

// ---------------- launcher ------------------------------------------------------
extern "C" void kernel_launch(void* const* d_in, const int* in_sizes, int n_in,
                              void* d_out, int out_size) {
    const float* x        = (const float*)d_in[0];
    const void*  ei       = d_in[1];
    const void*  batchraw = d_in[2];
    const float* W1       = (const float*)d_in[3];
    const float* att_src1 = (const float*)d_in[4];
    const float* att_dst1 = (const float*)d_in[5];
    const float* b1       = (const float*)d_in[6];
    const float* g1       = (const float*)d_in[7];
    const float* be1      = (const float*)d_in[8];
    const float* rm1      = (const float*)d_in[9];
    const float* rv1      = (const float*)d_in[10];
    const float* W2       = (const float*)d_in[11];
    const float* att_src2 = (const float*)d_in[12];
    const float* att_dst2 = (const float*)d_in[13];
    const float* b2       = (const float*)d_in[14];
    const float* g2       = (const float*)d_in[15];
    const float* be2      = (const float*)d_in[16];
    const float* rm2      = (const float*)d_in[17];
    const float* rv2      = (const float*)d_in[18];
    const float* lw1      = (const float*)d_in[19];
    const float* lb1      = (const float*)d_in[20];
    const float* lw2      = (const float*)d_in[21];
    const float* lb2      = (const float*)d_in[22];

    __half* p_hh = nullptr; __half* p_yh = nullptr; float* p_y = nullptr;
    __half* p_xh = nullptr; __half* p_wt1 = nullptr; __half* p_wt2 = nullptr;
    float4* p_as = nullptr; float4* p_ad = nullptr; int* p_deg = nullptr;
    int* p_rowptr = nullptr; int* p_cursor = nullptr; int* p_srcsort = nullptr;
    float* p_pooled = nullptr; int* p_src = nullptr; int* p_dst = nullptr;
    int* p_batch = nullptr; int* p_is64 = nullptr;
    int* p_bsum = nullptr; int* p_boff = nullptr;
    cudaGetSymbolAddress((void**)&p_hh, g_hh);
    cudaGetSymbolAddress((void**)&p_yh, g_yh);
    cudaGetSymbolAddress((void**)&p_y, g_y);
    cudaGetSymbolAddress((void**)&p_xh, g_xh);
    cudaGetSymbolAddress((void**)&p_wt1, g_wt1);
    cudaGetSymbolAddress((void**)&p_wt2, g_wt2);
    cudaGetSymbolAddress((void**)&p_as, g_as);
    cudaGetSymbolAddress((void**)&p_ad, g_ad);
    cudaGetSymbolAddress((void**)&p_deg, g_deg);
    cudaGetSymbolAddress((void**)&p_rowptr, g_rowptr);
    cudaGetSymbolAddress((void**)&p_cursor, g_cursor);
    cudaGetSymbolAddress((void**)&p_srcsort, g_srcsort);
    cudaGetSymbolAddress((void**)&p_pooled, g_pooled);
    cudaGetSymbolAddress((void**)&p_src, g_src);
    cudaGetSymbolAddress((void**)&p_dst, g_dst);
    cudaGetSymbolAddress((void**)&p_batch, g_batch);
    cudaGetSymbolAddress((void**)&p_is64, g_is64);
    cudaGetSymbolAddress((void**)&p_bsum, g_bsum);
    cudaGetSymbolAddress((void**)&p_boff, g_boff);

    float* p_asf = (float*)p_as;
    float* p_adf = (float*)p_ad;

    dim3 ggrid(HC / BN, (NN + BM - 1) / BM);
    int aggBlocks = (NN * 32 + 127) / 128;
    int pcBlocks = (NN * FIN / 4 + 255) / 256;

    // (1) detect (2) preconv (3) prep(+count) (4) hgemm1 <- profiled sentinel
    detect_kernel<<<1, 1024>>>((const unsigned*)ei, p_is64);
    preconv_kernel<<<pcBlocks, 256>>>(x, W1, W2, p_xh, p_wt1, p_wt2, p_deg,
                                      p_asf, p_adf);
    prep_kernel<<<(EE + 255) / 256, 256>>>(ei, batchraw, p_is64, p_src, p_dst,
                                           p_batch, p_deg);
    hgemm_kernel<<<ggrid, 256>>>(p_xh, p_wt1, p_hh, att_src1, att_dst1,
                                 p_asf, p_adf, NN, FIN);

    // hierarchical scan + fill
    blocksum_kernel<<<NB, SCAN_B>>>(p_deg, p_bsum);
    scanb_kernel<<<1, 256>>>(p_bsum, p_boff);
    scatter_kernel<<<NB, SCAN_B>>>(p_deg, p_boff, p_rowptr, p_cursor);
    fill_kernel<<<(ET + 255) / 256, 256>>>(p_src, p_dst, p_cursor, p_srcsort);

    // ---- layer 1 ----
    agg_kernel<<<aggBlocks, 128>>>(p_srcsort, p_hh, p_as, p_ad, p_rowptr,
                                   p_yh, (float*)nullptr,
                                   b1, g1, be1, rm1, rv1);

    // ---- layer 2 ----
    zeroasad_kernel<<<(NN * 4 + 255) / 256, 256>>>(p_asf, p_adf);
    hgemm_kernel<<<ggrid, 256>>>(p_yh, p_wt2, p_hh, att_src2, att_dst2,
                                 p_asf, p_adf, NN, HC);
    agg_kernel<<<aggBlocks, 128>>>(p_srcsort, p_hh, p_as, p_ad, p_rowptr,
                                   p_yh, p_y,
                                   b2, g2, be2, rm2, rv2);

    // ---- pool + head ----
    pool_kernel<<<NG, 256>>>(p_batch, p_y, p_pooled);
    head_kernel<<<NG, 128>>>(p_pooled, lw1, lb1, lw2, lb2, (float*)d_out);
}

// round 13
// speedup vs baseline: 1.2328x; 1.0941x over previous
#include <cuda_runtime.h>
#include <cuda_fp16.h>
#include <math.h>

#define NN 50000
#define EE 800000
#define ET 850000      // EE + NN self loops
#define FIN 128
#define HC 256         // HEADS*HID
#define NG 500
#define SLOPE 0.2f
#define BNEPS 1e-5f

// ---------------- scratch (device globals; no runtime allocation) -------------
__device__ __align__(256) __half g_hh[(size_t)NN * HC];   // GEMM output (fp16)
__device__ __align__(256) __half g_yh[(size_t)NN * HC];   // layer output (fp16)
__device__ __align__(256) __half g_xh[(size_t)NN * FIN];  // x converted to fp16
__device__ __align__(256) __half g_wt1[HC * FIN];         // W1^T fp16 [n][k]
__device__ __align__(256) __half g_wt2[HC * HC];          // W2^T fp16 [n][k]
__device__ float4 g_as[NN];
__device__ float4 g_ad[NN];
__device__ int    g_srcsort[ET];
__device__ int    g_deg[NN];
__device__ int    g_rowptr[NN + 1];
__device__ int    g_cursor[NN];
__device__ __align__(256) float  g_pooled[NG * HC];
__device__ int    g_src[EE];
__device__ int    g_dst[EE];
__device__ int    g_batch[NN];
__device__ int    g_is64;
#define SCAN_B 256
#define NB ((NN + SCAN_B - 1) / SCAN_B)    // 196
__device__ int    g_bsum[NB];
__device__ int    g_boff[NB];

// ---------------- dtype detect ------------------------------------------------
__global__ void detect_kernel(const unsigned* __restrict__ eiw, int* __restrict__ is64) {
    __shared__ int s_any;
    if (threadIdx.x == 0) s_any = 0;
    __syncthreads();
    unsigned v = eiw[threadIdx.x * 2 + 1];
    if (v != 0u) atomicOr(&s_any, 1);
    __syncthreads();
    if (threadIdx.x == 0) *is64 = s_any ? 0 : 1;
}

// ------- preconvert: x->fp16, W^T fp16, deg=1, zero as/ad ----------------------
__global__ void preconv_kernel(const float* __restrict__ x,
                               const float* __restrict__ W1,
                               const float* __restrict__ W2,
                               __half* __restrict__ xh,
                               __half* __restrict__ wt1,
                               __half* __restrict__ wt2,
                               int* __restrict__ deg,
                               float* __restrict__ asf,
                               float* __restrict__ adf) {
    int i = blockIdx.x * blockDim.x + threadIdx.x;
    int i4 = i * 4;
    if (i4 < NN * FIN) {
        float4 v = *(const float4*)(x + i4);
        __half2* o = (__half2*)(xh + i4);
        o[0] = __floats2half2_rn(v.x, v.y);
        o[1] = __floats2half2_rn(v.z, v.w);
    }
    if (i < NN) deg[i] = 1;
    if (i < NN * 4) { asf[i] = 0.f; adf[i] = 0.f; }
    if (i < HC * HC) {
        int n = i >> 8, k = i & 255;
        wt2[n * HC + k] = __float2half_rn(W2[k * HC + n]);
    }
    if (i < HC * FIN) {
        int n = i / FIN, k = i % FIN;
        wt1[n * FIN + k] = __float2half_rn(W1[k * HC + n]);
    }
}

// ---------------- zero as/ad between layers ------------------------------------
__global__ void zeroasad_kernel(float* __restrict__ asf, float* __restrict__ adf) {
    int i = blockIdx.x * blockDim.x + threadIdx.x;
    if (i < NN * 4) { asf[i] = 0.f; adf[i] = 0.f; }
}

// ---------------- prep: index conversion + batch + degree count ----------------
__global__ void prep_kernel(const void* __restrict__ ei, const void* __restrict__ b,
                            const int* __restrict__ is64,
                            int* __restrict__ src, int* __restrict__ dst,
                            int* __restrict__ batch, int* __restrict__ deg) {
    int i = blockIdx.x * blockDim.x + threadIdx.x;
    int w = *is64;
    if (i < EE) {
        int s, d;
        if (w) {
            const long long* p = (const long long*)ei;
            s = (int)p[i];
            d = (int)p[EE + i];
        } else {
            const int* p = (const int*)ei;
            s = p[i];
            d = p[EE + i];
        }
        src[i] = s;
        dst[i] = d;
        atomicAdd(&deg[d], 1);
    }
    if (i < NN) {
        batch[i] = w ? (int)((const long long*)b)[i] : ((const int*)b)[i];
    }
}

// ---------------- hierarchical scan -------------------------------------------
__global__ void blocksum_kernel(const int* __restrict__ deg, int* __restrict__ bsum) {
    __shared__ int sd[SCAN_B];
    int tid = threadIdx.x;
    int i = blockIdx.x * SCAN_B + tid;
    sd[tid] = (i < NN) ? deg[i] : 0;
    __syncthreads();
    for (int off = SCAN_B / 2; off; off >>= 1) {
        if (tid < off) sd[tid] += sd[tid + off];
        __syncthreads();
    }
    if (tid == 0) bsum[blockIdx.x] = sd[0];
}

__global__ void scanb_kernel(const int* __restrict__ bsum, int* __restrict__ boff) {
    __shared__ int sd[256];
    int tid = threadIdx.x;
    int v = (tid < NB) ? bsum[tid] : 0;
    sd[tid] = v;
    __syncthreads();
    for (int off = 1; off < 256; off <<= 1) {
        int t = (tid >= off) ? sd[tid - off] : 0;
        __syncthreads();
        sd[tid] += t;
        __syncthreads();
    }
    if (tid < NB) boff[tid] = sd[tid] - v;
}

__global__ void scatter_kernel(const int* __restrict__ deg, const int* __restrict__ boff,
                               int* __restrict__ rowptr, int* __restrict__ cursor) {
    __shared__ int sd[SCAN_B];
    int tid = threadIdx.x;
    int i = blockIdx.x * SCAN_B + tid;
    int v = (i < NN) ? deg[i] : 0;
    sd[tid] = v;
    __syncthreads();
    for (int off = 1; off < SCAN_B; off <<= 1) {
        int t = (tid >= off) ? sd[tid - off] : 0;
        __syncthreads();
        sd[tid] += t;
        __syncthreads();
    }
    int base = boff[blockIdx.x];
    if (i < NN) {
        rowptr[i + 1] = base + sd[tid];
        cursor[i] = base + sd[tid] - v;
    }
    if (i == 0) rowptr[0] = 0;
}

__global__ void fill_kernel(const int* __restrict__ esrc, const int* __restrict__ edst,
                            int* __restrict__ cursor, int* __restrict__ srcsort) {
    int eid = blockIdx.x * blockDim.x + threadIdx.x;
    if (eid >= ET) return;
    int s, d;
    if (eid < EE) { s = esrc[eid]; d = edst[eid]; }
    else          { s = eid - EE; d = s; }
    int pos = atomicAdd(&cursor[d], 1);
    srcsort[pos] = s;
}

// ------ fp16 tensor-core GEMM (3-stage cp.async) + fused logit epilogue --------
#define BM 128
#define BN 128
#define HS 24          // smem row stride (halves)
#define BUFB (BM * HS) // halves per buffer

__device__ __forceinline__ void cp16(unsigned saddr, const void* gptr) {
    asm volatile("cp.async.cg.shared.global [%0], [%1], 16;\n"
                 :: "r"(saddr), "l"(gptr));
}

__global__ __launch_bounds__(256) void hgemm_kernel(const __half* __restrict__ A,
                                                    const __half* __restrict__ Bt,
                                                    __half* __restrict__ C,
                                                    const float* __restrict__ att_src,
                                                    const float* __restrict__ att_dst,
                                                    float* __restrict__ asf,
                                                    float* __restrict__ adf,
                                                    int M, int K) {
    __shared__ __half As[3][BUFB];
    __shared__ __half Bs[3][BUFB];

    int tid = threadIdx.x;
    int warp = tid >> 5, lane = tid & 31;
    int warpM = (warp & 3) * 32;
    int warpN = (warp >> 2) * 64;
    int rowBase = blockIdx.y * BM;
    int colBase = blockIdx.x * BN;

    int fr = tid >> 1;
    int fk = (tid & 1) * 8;
    int gr = rowBase + fr;
    int grc = (gr < M) ? gr : (M - 1);     // clamp; OOB rows never stored

    unsigned sAs, sBs;
    {
        unsigned a;
        asm("{ .reg .u64 t; cvta.to.shared.u64 t, %1; cvt.u32.u64 %0, t; }"
            : "=r"(a) : "l"(&As[0][0]));
        sAs = a + (fr * HS + fk) * 2;
        asm("{ .reg .u64 t; cvta.to.shared.u64 t, %1; cvt.u32.u64 %0, t; }"
            : "=r"(a) : "l"(&Bs[0][0]));
        sBs = a + (fr * HS + fk) * 2;
    }
    const __half* Arow = A + (size_t)grc * K + fk;
    const __half* Brow = Bt + (size_t)(colBase + fr) * K + fk;

    int T = K / 16;

    // prologue: prefetch tiles 0,1
    cp16(sAs, Arow);
    cp16(sBs, Brow);
    asm volatile("cp.async.commit_group;\n");
    cp16(sAs + BUFB * 2, Arow + 16);
    cp16(sBs + BUFB * 2, Brow + 16);
    asm volatile("cp.async.commit_group;\n");

    float d[2][8][4];
#pragma unroll
    for (int i = 0; i < 2; i++)
#pragma unroll
        for (int j = 0; j < 8; j++)
#pragma unroll
            for (int q = 0; q < 4; q++) d[i][j][q] = 0.f;

    int lr = lane >> 2;
    int lc = lane & 3;

    for (int t = 0; t < T; t++) {
        asm volatile("cp.async.wait_group 1;\n");
        __syncthreads();
        int buf = t % 3;

        unsigned af[2][4], bf[8][2];
#pragma unroll
        for (int mt = 0; mt < 2; mt++) {
            int r = warpM + 16 * mt + lr;
            af[mt][0] = *(const unsigned*)(&As[buf][r * HS + 2 * lc]);
            af[mt][1] = *(const unsigned*)(&As[buf][(r + 8) * HS + 2 * lc]);
            af[mt][2] = *(const unsigned*)(&As[buf][r * HS + 2 * lc + 8]);
            af[mt][3] = *(const unsigned*)(&As[buf][(r + 8) * HS + 2 * lc + 8]);
        }
#pragma unroll
        for (int nt = 0; nt < 8; nt++) {
            int n = warpN + 8 * nt + lr;
            bf[nt][0] = *(const unsigned*)(&Bs[buf][n * HS + 2 * lc]);
            bf[nt][1] = *(const unsigned*)(&Bs[buf][n * HS + 2 * lc + 8]);
        }
#pragma unroll
        for (int mt = 0; mt < 2; mt++)
#pragma unroll
            for (int nt = 0; nt < 8; nt++) {
                asm volatile(
                    "mma.sync.aligned.m16n8k16.row.col.f32.f16.f16.f32 "
                    "{%0,%1,%2,%3}, {%4,%5,%6,%7}, {%8,%9}, {%0,%1,%2,%3};"
                    : "+f"(d[mt][nt][0]), "+f"(d[mt][nt][1]),
                      "+f"(d[mt][nt][2]), "+f"(d[mt][nt][3])
                    : "r"(af[mt][0]), "r"(af[mt][1]), "r"(af[mt][2]), "r"(af[mt][3]),
                      "r"(bf[nt][0]), "r"(bf[nt][1]));
            }

        // prefetch tile t+2 into buf (t+2)%3 (safe: all warps past sync above)
        if (t + 2 < T) {
            int nb = (t + 2) % 3;
            int k0 = (t + 2) * 16;
            cp16(sAs + nb * BUFB * 2, Arow + k0);
            cp16(sBs + nb * BUFB * 2, Brow + k0);
        }
        asm volatile("cp.async.commit_group;\n");
    }

    // epilogue: store fp16 + fused attention-logit partial dots
    int hidx = (colBase + warpN) >> 6;   // warp's 64 columns = one head
#pragma unroll
    for (int mt = 0; mt < 2; mt++) {
        int r0 = rowBase + warpM + 16 * mt + lr;
        int r1 = r0 + 8;
        float s0 = 0.f, s1 = 0.f, t0 = 0.f, t1 = 0.f;
#pragma unroll
        for (int nt = 0; nt < 8; nt++) {
            int c = colBase + warpN + 8 * nt + 2 * lc;
            float2 sv = *(const float2*)(att_src + c);
            float2 dv = *(const float2*)(att_dst + c);
            s0 = fmaf(d[mt][nt][0], sv.x, fmaf(d[mt][nt][1], sv.y, s0));
            s1 = fmaf(d[mt][nt][2], sv.x, fmaf(d[mt][nt][3], sv.y, s1));
            t0 = fmaf(d[mt][nt][0], dv.x, fmaf(d[mt][nt][1], dv.y, t0));
            t1 = fmaf(d[mt][nt][2], dv.x, fmaf(d[mt][nt][3], dv.y, t1));
            if (r0 < M)
                *(__half2*)(C + (size_t)r0 * HC + c) = __floats2half2_rn(d[mt][nt][0], d[mt][nt][1]);
            if (r1 < M)
                *(__half2*)(C + (size_t)r1 * HC + c) = __floats2half2_rn(d[mt][nt][2], d[mt][nt][3]);
        }
#pragma unroll
        for (int off = 1; off < 4; off <<= 1) {
            s0 += __shfl_xor_sync(0xFFFFFFFFu, s0, off);
            s1 += __shfl_xor_sync(0xFFFFFFFFu, s1, off);
            t0 += __shfl_xor_sync(0xFFFFFFFFu, t0, off);
            t1 += __shfl_xor_sync(0xFFFFFFFFu, t1, off);
        }
        if (lc == 0) {
            if (r0 < M) {
                atomicAdd(&asf[r0 * 4 + hidx], s0);
                atomicAdd(&adf[r0 * 4 + hidx], t0);
            }
            if (r1 < M) {
                atomicAdd(&asf[r1 * 4 + hidx], s1);
                atomicAdd(&adf[r1 * 4 + hidx], t1);
            }
        }
    }
}

// ---------------- fused single-pass softmax-aggregation + bias + relu + BN -----
__device__ __forceinline__ float4 leaky4(float4 a, float4 b) {
    float4 e;
    float v;
    v = a.x + b.x; e.x = (v > 0.f) ? v : SLOPE * v;
    v = a.y + b.y; e.y = (v > 0.f) ? v : SLOPE * v;
    v = a.z + b.z; e.z = (v > 0.f) ? v : SLOPE * v;
    v = a.w + b.w; e.w = (v > 0.f) ? v : SLOPE * v;
    return e;
}

__global__ __launch_bounds__(128) void agg_kernel(const int* __restrict__ srcsort,
                                                  const __half* __restrict__ hh,
                                                  const float4* __restrict__ as_in,
                                                  const float4* __restrict__ ad_in,
                                                  const int* __restrict__ rowptr,
                                                  __half* __restrict__ yh,
                                                  const float* __restrict__ bias,
                                                  const float* __restrict__ gam,
                                                  const float* __restrict__ bet,
                                                  const float* __restrict__ rmean,
                                                  const float* __restrict__ rvar) {
    int warp = (blockIdx.x * blockDim.x + threadIdx.x) >> 5;
    int lid = threadIdx.x & 31;
    if (warp >= NN) return;
    int beg = rowptr[warp], end = rowptr[warp + 1];
    float4 ad4 = ad_in[warp];

    float accx[4] = {0.f, 0.f, 0.f, 0.f};
    float accy[4] = {0.f, 0.f, 0.f, 0.f};
    float sp[4] = {0.f, 0.f, 0.f, 0.f};

    for (int base = beg; base < end; base += 32) {
        int j = base + lid;
        bool valid = j < end;
        int src = valid ? srcsort[j] : 0;
        float4 e4 = leaky4(as_in[src], ad4);
        float4 al;
        al.x = valid ? __expf(e4.x) : 0.f;
        al.y = valid ? __expf(e4.y) : 0.f;
        al.z = valid ? __expf(e4.z) : 0.f;
        al.w = valid ? __expf(e4.w) : 0.f;
        sp[0] += al.x; sp[1] += al.y; sp[2] += al.z; sp[3] += al.w;

        int nn = min(32, end - base);
        for (int i = 0; i < nn; i++) {
            int sj   = __shfl_sync(0xFFFFFFFFu, src, i);
            float a0 = __shfl_sync(0xFFFFFFFFu, al.x, i);
            float a1 = __shfl_sync(0xFFFFFFFFu, al.y, i);
            float a2 = __shfl_sync(0xFFFFFFFFu, al.z, i);
            float a3 = __shfl_sync(0xFFFFFFFFu, al.w, i);
            const __half2* hs = (const __half2*)(hh + (size_t)sj * HC);
            float2 v0 = __half22float2(hs[lid]);
            float2 v1 = __half22float2(hs[lid + 32]);
            float2 v2 = __half22float2(hs[lid + 64]);
            float2 v3 = __half22float2(hs[lid + 96]);
            accx[0] = fmaf(v0.x, a0, accx[0]);  accy[0] = fmaf(v0.y, a0, accy[0]);
            accx[1] = fmaf(v1.x, a1, accx[1]);  accy[1] = fmaf(v1.y, a1, accy[1]);
            accx[2] = fmaf(v2.x, a2, accx[2]);  accy[2] = fmaf(v2.y, a2, accy[2]);
            accx[3] = fmaf(v3.x, a3, accx[3]);  accy[3] = fmaf(v3.y, a3, accy[3]);
        }
    }

#pragma unroll
    for (int off = 16; off; off >>= 1) {
#pragma unroll
        for (int k = 0; k < 4; k++)
            sp[k] += __shfl_xor_sync(0xFFFFFFFFu, sp[k], off);
    }
    float inv[4];
#pragma unroll
    for (int k = 0; k < 4; k++) inv[k] = 1.f / sp[k];

    size_t ob = (size_t)warp * HC;
#pragma unroll
    for (int k = 0; k < 4; k++) {
        int c = 2 * lid + 64 * k;
        float2 bi = *(const float2*)(bias + c);
        float2 ga = *(const float2*)(gam + c);
        float2 be = *(const float2*)(bet + c);
        float2 rm = *(const float2*)(rmean + c);
        float2 rv = *(const float2*)(rvar + c);
        float vx = fmaxf(accx[k] * inv[k] + bi.x, 0.f);
        float vy = fmaxf(accy[k] * inv[k] + bi.y, 0.f);
        vx = (vx - rm.x) * rsqrtf(rv.x + BNEPS) * ga.x + be.x;
        vy = (vy - rm.y) * rsqrtf(rv.y + BNEPS) * ga.y + be.y;
        *(__half2*)(yh + ob + c) = __floats2half2_rn(vx, vy);
    }
}

// ---------------- pooling (fp16 in, fp32 accumulate) ---------------------------
__device__ __forceinline__ int lowerb(const int* b, int n, int key) {
    int lo = 0, hi = n;
    while (lo < hi) {
        int mid = (lo + hi) >> 1;
        if (b[mid] < key) lo = mid + 1; else hi = mid;
    }
    return lo;
}

__global__ void pool_kernel(const int* __restrict__ batch,
                            const __half* __restrict__ yh,
                            float* __restrict__ pooled) {
    int g = blockIdx.x;
    int c = threadIdx.x;     // 128 threads, each owns a half2 channel pair
    __shared__ int s_lo, s_hi;
    if (c == 0) {
        s_lo = lowerb(batch, NN, g);
        s_hi = lowerb(batch, NN, g + 1);
    }
    __syncthreads();
    float sx = 0.f, sy = 0.f;
    const __half2* base = (const __half2*)yh;
    for (int n = s_lo; n < s_hi; n++) {
        float2 v = __half22float2(base[(size_t)n * (HC / 2) + c]);
        sx += v.x;
        sy += v.y;
    }
    int cnt = s_hi - s_lo;
    float denom = (cnt > 0) ? (float)cnt : 1.f;
    *(float2*)(pooled + g * HC + 2 * c) = make_float2(sx / denom, sy / denom);
}

// ---------------- MLP head -----------------------------------------------------
__global__ void head_kernel(const float* __restrict__ pooled,
                            const float* __restrict__ lw1, const float* __restrict__ lb1,
                            const float* __restrict__ lw2, const float* __restrict__ lb2,
                            float* __restrict__ out) {
    int g = blockIdx.x;
    int j = threadIdx.x;
    __shared__ float sp[256];
    __shared__ float r0[128], r1[128];
    sp[j] = pooled[g * HC + j];
    sp[j + 128] = pooled[g * HC + 128 + j];
    __syncthreads();
    float z = lb1[j];
#pragma unroll 4
    for (int k = 0; k < 256; k++) z = fmaf(sp[k], lw1[k * 128 + j], z);
    z = fmaxf(z, 0.f);
    r0[j] = z * lw2[j * 2 + 0];
    r1[j] = z * lw2[j * 2 + 1];
    __syncthreads();
    for (int off = 64; off; off >>= 1) {
        if (j < off) { r0[j] += r0[j + off]; r1[j] += r1[j + off]; }
        __syncthreads();
    }
    if (j == 0) {
        out[g * 2 + 0] = r0[0] + lb2[0];
        out[g * 2 + 1] = r1[0] + lb2[1];
    }
}

// ---------------- launcher ------------------------------------------------------
extern "C" void kernel_launch(void* const* d_in, const int* in_sizes, int n_in,
                              void* d_out, int out_size) {
    const float* x        = (const float*)d_in[0];
    const void*  ei       = d_in[1];
    const void*  batchraw = d_in[2];
    const float* W1       = (const float*)d_in[3];
    const float* att_src1 = (const float*)d_in[4];
    const float* att_dst1 = (const float*)d_in[5];
    const float* b1       = (const float*)d_in[6];
    const float* g1       = (const float*)d_in[7];
    const float* be1      = (const float*)d_in[8];
    const float* rm1      = (const float*)d_in[9];
    const float* rv1      = (const float*)d_in[10];
    const float* W2       = (const float*)d_in[11];
    const float* att_src2 = (const float*)d_in[12];
    const float* att_dst2 = (const float*)d_in[13];
    const float* b2       = (const float*)d_in[14];
    const float* g2       = (const float*)d_in[15];
    const float* be2      = (const float*)d_in[16];
    const float* rm2      = (const float*)d_in[17];
    const float* rv2      = (const float*)d_in[18];
    const float* lw1      = (const float*)d_in[19];
    const float* lb1      = (const float*)d_in[20];
    const float* lw2      = (const float*)d_in[21];
    const float* lb2      = (const float*)d_in[22];

    __half* p_hh = nullptr; __half* p_yh = nullptr;
    __half* p_xh = nullptr; __half* p_wt1 = nullptr; __half* p_wt2 = nullptr;
    float4* p_as = nullptr; float4* p_ad = nullptr; int* p_deg = nullptr;
    int* p_rowptr = nullptr; int* p_cursor = nullptr; int* p_srcsort = nullptr;
    float* p_pooled = nullptr; int* p_src = nullptr; int* p_dst = nullptr;
    int* p_batch = nullptr; int* p_is64 = nullptr;
    int* p_bsum = nullptr; int* p_boff = nullptr;
    cudaGetSymbolAddress((void**)&p_hh, g_hh);
    cudaGetSymbolAddress((void**)&p_yh, g_yh);
    cudaGetSymbolAddress((void**)&p_xh, g_xh);
    cudaGetSymbolAddress((void**)&p_wt1, g_wt1);
    cudaGetSymbolAddress((void**)&p_wt2, g_wt2);
    cudaGetSymbolAddress((void**)&p_as, g_as);
    cudaGetSymbolAddress((void**)&p_ad, g_ad);
    cudaGetSymbolAddress((void**)&p_deg, g_deg);
    cudaGetSymbolAddress((void**)&p_rowptr, g_rowptr);
    cudaGetSymbolAddress((void**)&p_cursor, g_cursor);
    cudaGetSymbolAddress((void**)&p_srcsort, g_srcsort);
    cudaGetSymbolAddress((void**)&p_pooled, g_pooled);
    cudaGetSymbolAddress((void**)&p_src, g_src);
    cudaGetSymbolAddress((void**)&p_dst, g_dst);
    cudaGetSymbolAddress((void**)&p_batch, g_batch);
    cudaGetSymbolAddress((void**)&p_is64, g_is64);
    cudaGetSymbolAddress((void**)&p_bsum, g_bsum);
    cudaGetSymbolAddress((void**)&p_boff, g_boff);

    float* p_asf = (float*)p_as;
    float* p_adf = (float*)p_ad;

    dim3 ggrid(HC / BN, (NN + BM - 1) / BM);
    int aggBlocks = (NN * 32 + 127) / 128;
    int pcBlocks = (NN * FIN / 4 + 255) / 256;

    // (1) detect (2) preconv (3) prep(+count) (4) hgemm1 <- profiled sentinel
    detect_kernel<<<1, 1024>>>((const unsigned*)ei, p_is64);
    preconv_kernel<<<pcBlocks, 256>>>(x, W1, W2, p_xh, p_wt1, p_wt2, p_deg,
                                      p_asf, p_adf);
    prep_kernel<<<(EE + 255) / 256, 256>>>(ei, batchraw, p_is64, p_src, p_dst,
                                           p_batch, p_deg);
    hgemm_kernel<<<ggrid, 256>>>(p_xh, p_wt1, p_hh, att_src1, att_dst1,
                                 p_asf, p_adf, NN, FIN);

    // hierarchical scan + fill
    blocksum_kernel<<<NB, SCAN_B>>>(p_deg, p_bsum);
    scanb_kernel<<<1, 256>>>(p_bsum, p_boff);
    scatter_kernel<<<NB, SCAN_B>>>(p_deg, p_boff, p_rowptr, p_cursor);
    fill_kernel<<<(ET + 255) / 256, 256>>>(p_src, p_dst, p_cursor, p_srcsort);

    // ---- layer 1 ----
    agg_kernel<<<aggBlocks, 128>>>(p_srcsort, p_hh, p_as, p_ad, p_rowptr, p_yh,
                                   b1, g1, be1, rm1, rv1);

    // ---- layer 2 ----
    zeroasad_kernel<<<(NN * 4 + 255) / 256, 256>>>(p_asf, p_adf);
    hgemm_kernel<<<ggrid, 256>>>(p_yh, p_wt2, p_hh, att_src2, att_dst2,
                                 p_asf, p_adf, NN, HC);
    agg_kernel<<<aggBlocks, 128>>>(p_srcsort, p_hh, p_as, p_ad, p_rowptr, p_yh,
                                   b2, g2, be2, rm2, rv2);

    // ---- pool + head ----
    pool_kernel<<<NG, 128>>>(p_batch, p_yh, p_pooled);
    head_kernel<<<NG, 128>>>(p_pooled, lw1, lb1, lw2, lb2, (float*)d_out);
}